// round 2
// baseline (speedup 1.0000x reference)
#include <cuda_runtime.h>
#include <math.h>

#define D        128
#define N_DST    100000
#define N_SRC0   400000
#define N_SRC1   10000
#define K0       8
#define K1       4

// ---------------- scratch (device globals; no allocation allowed) ----------------
__device__ float g_wl0[D], g_wr0[D], g_wl1[D], g_wr1[D];
__device__ float g_WfcT[D * D];                    // WfcT[k*D+j] = Wfc[j*D+k]
__device__ float g_el0[N_SRC0];
__device__ float g_el1[N_SRC1];
__device__ float g_er0[N_DST];
__device__ float g_er1[N_DST];
__device__ float g_agg0[N_DST * D];
__device__ float g_agg1[N_DST * D];
__device__ float g_e0[N_DST * D];
__device__ float g_e1[N_DST * D];
__device__ float g_sp[2 * D];
__device__ float g_beta[2];

// ---------------- prep: w vectors, Wfc transpose, zero sp accumulators ----------
__global__ void prep_kernel(const float* __restrict__ Ws0, const float* __restrict__ al0,
                            const float* __restrict__ Wd0, const float* __restrict__ ar0,
                            const float* __restrict__ Ws1, const float* __restrict__ al1,
                            const float* __restrict__ Wd1, const float* __restrict__ ar1,
                            const float* __restrict__ Wfc) {
    int i = threadIdx.x;  // 0..127
    float s0 = 0.f, s1 = 0.f, s2 = 0.f, s3 = 0.f;
    for (int k = 0; k < D; k++) {
        s0 += Ws0[i * D + k] * al0[k];
        s1 += Wd0[i * D + k] * ar0[k];
        s2 += Ws1[i * D + k] * al1[k];
        s3 += Wd1[i * D + k] * ar1[k];
    }
    g_wl0[i] = s0; g_wr0[i] = s1; g_wl1[i] = s2; g_wr1[i] = s3;
    g_sp[i] = 0.f; g_sp[D + i] = 0.f;
    for (int j = 0; j < D; j++) g_WfcT[i * D + j] = Wfc[j * D + i];
}

// ---------------- GEMV: out[i] = dot(X[i,:], wv) -------------------------------
__global__ void gemv_el(const float* __restrict__ X, int n,
                        const float* __restrict__ wv, float* __restrict__ out) {
    __shared__ float4 sw[32];
    int t = threadIdx.x;
    if (t < 32) sw[t] = ((const float4*)wv)[t];
    __syncthreads();
    int lane = t & 31;
    int row  = (blockIdx.x * blockDim.x + t) >> 5;
    if (row >= n) return;
    float4 x  = ((const float4*)X)[row * 32 + lane];
    float4 w  = sw[lane];
    float  s  = x.x * w.x + x.y * w.y + x.z * w.z + x.w * w.w;
    #pragma unroll
    for (int o = 16; o; o >>= 1) s += __shfl_xor_sync(0xffffffffu, s, o);
    if (lane == 0) out[row] = s;
}

// ---------------- GEMV x2: er0/er1 from h_dst in one pass ----------------------
__global__ void gemv_er(const float* __restrict__ X,
                        const float* __restrict__ wv0, const float* __restrict__ wv1,
                        float* __restrict__ out0, float* __restrict__ out1) {
    __shared__ float4 sw0[32], sw1[32];
    int t = threadIdx.x;
    if (t < 32) { sw0[t] = ((const float4*)wv0)[t]; sw1[t] = ((const float4*)wv1)[t]; }
    __syncthreads();
    int lane = t & 31;
    int row  = (blockIdx.x * blockDim.x + t) >> 5;
    if (row >= N_DST) return;
    float4 x  = ((const float4*)X)[row * 32 + lane];
    float4 w0 = sw0[lane], w1 = sw1[lane];
    float  s0 = x.x * w0.x + x.y * w0.y + x.z * w0.z + x.w * w0.w;
    float  s1 = x.x * w1.x + x.y * w1.y + x.z * w1.z + x.w * w1.w;
    #pragma unroll
    for (int o = 16; o; o >>= 1) {
        s0 += __shfl_xor_sync(0xffffffffu, s0, o);
        s1 += __shfl_xor_sync(0xffffffffu, s1, o);
    }
    if (lane == 0) { out0[row] = s0; out1[row] = s1; }
}

// ---------------- gather + edge softmax + h-space aggregation ------------------
template <int K>
__global__ void gat_agg(const float* __restrict__ hsrc, const int* __restrict__ idx,
                        const float* __restrict__ el, const float* __restrict__ er,
                        float* __restrict__ agg) {
    int t    = threadIdx.x;
    int lane = t & 31;
    int row  = (blockIdx.x * blockDim.x + t) >> 5;
    if (row >= N_DST) return;

    int   id = 0;
    float e  = 0.f;
    if (lane < K) {
        id = idx[row * K + lane];
        e  = el[id] + er[row];
        e  = e > 0.f ? e : 0.2f * e;   // leaky relu 0.2
    }
    float m = -1e30f;
    #pragma unroll
    for (int j = 0; j < K; j++) m = fmaxf(m, __shfl_sync(0xffffffffu, e, j));
    float a[K];
    float denom = 0.f;
    #pragma unroll
    for (int j = 0; j < K; j++) {
        a[j] = __expf(__shfl_sync(0xffffffffu, e, j) - m);
        denom += a[j];
    }
    float inv = 1.f / denom;
    float4 acc = make_float4(0.f, 0.f, 0.f, 0.f);
    #pragma unroll
    for (int j = 0; j < K; j++) {
        int    ij = __shfl_sync(0xffffffffu, id, j);
        float4 x  = ((const float4*)hsrc)[ij * 32 + lane];
        float  aj = a[j] * inv;
        acc.x += aj * x.x; acc.y += aj * x.y; acc.z += aj * x.z; acc.w += aj * x.w;
    }
    ((float4*)agg)[row * 32 + lane] = acc;
}

// ---------------- GEMM: Y[n,128] = X[n,128] @ W[128,128] + bias ----------------
// block: 256 threads; tile 64 rows; thread (tx=t%32 -> 4 cols, ty=t/32 -> 8 rows)
__global__ void gemm_e(const float* __restrict__ X, const float* __restrict__ W,
                       const float* __restrict__ bias, float* __restrict__ Y, int n) {
    extern __shared__ float smem[];
    float* sW = smem;            // 128*128
    float* sX = smem + D * D;    // 64*128
    int t = threadIdx.x;
    {
        float4*       sW4 = (float4*)sW;
        const float4* W4  = (const float4*)W;
        for (int i = t; i < D * D / 4; i += 256) sW4[i] = W4[i];
    }
    int tx   = t & 31;
    int ty   = t >> 5;
    int row0 = blockIdx.x * 64;
    {
        const float4* X4  = (const float4*)X;
        float4*       sX4 = (float4*)sX;
        for (int i = t; i < 64 * 32; i += 256) {
            int r = i >> 5, c = i & 31;
            float4 v = make_float4(0.f, 0.f, 0.f, 0.f);
            if (row0 + r < n) v = X4[(row0 + r) * 32 + c];
            sX4[i] = v;
        }
    }
    __syncthreads();
    float acc[8][4];
    #pragma unroll
    for (int r = 0; r < 8; r++)
        #pragma unroll
        for (int c = 0; c < 4; c++) acc[r][c] = 0.f;

    const float4* sW4 = (const float4*)sW;
    #pragma unroll 4
    for (int k = 0; k < D; k++) {
        float4 w4 = sW4[k * 32 + tx];
        #pragma unroll
        for (int r = 0; r < 8; r++) {
            float xv = sX[(ty * 8 + r) * D + k];
            acc[r][0] += xv * w4.x; acc[r][1] += xv * w4.y;
            acc[r][2] += xv * w4.z; acc[r][3] += xv * w4.w;
        }
    }
    float4 b4 = ((const float4*)bias)[tx];
    #pragma unroll
    for (int r = 0; r < 8; r++) {
        int row = row0 + ty * 8 + r;
        if (row < n) {
            float4 o = make_float4(acc[r][0] + b4.x, acc[r][1] + b4.y,
                                   acc[r][2] + b4.z, acc[r][3] + b4.w);
            ((float4*)Y)[row * 32 + tx] = o;
        }
    }
}

// ---------------- GEMM + tanh + column-mean accumulation -----------------------
// sp += sum_rows tanh(X @ WfcT_cols + bias)   (Wt is already transposed: Wt[k*D+j])
__global__ void gemm_sp(const float* __restrict__ X, const float* __restrict__ Wt,
                        const float* __restrict__ bias, float* __restrict__ spout, int n) {
    extern __shared__ float smem[];
    float* sW = smem;
    float* sX = smem + D * D;
    int t = threadIdx.x;
    {
        float4*       sW4 = (float4*)sW;
        const float4* W4  = (const float4*)Wt;
        for (int i = t; i < D * D / 4; i += 256) sW4[i] = W4[i];
    }
    int tx   = t & 31;
    int ty   = t >> 5;
    int row0 = blockIdx.x * 64;
    {
        const float4* X4  = (const float4*)X;
        float4*       sX4 = (float4*)sX;
        for (int i = t; i < 64 * 32; i += 256) {
            int r = i >> 5, c = i & 31;
            float4 v = make_float4(0.f, 0.f, 0.f, 0.f);
            if (row0 + r < n) v = X4[(row0 + r) * 32 + c];
            sX4[i] = v;
        }
    }
    __syncthreads();
    float acc[8][4];
    #pragma unroll
    for (int r = 0; r < 8; r++)
        #pragma unroll
        for (int c = 0; c < 4; c++) acc[r][c] = 0.f;

    const float4* sW4 = (const float4*)sW;
    #pragma unroll 4
    for (int k = 0; k < D; k++) {
        float4 w4 = sW4[k * 32 + tx];
        #pragma unroll
        for (int r = 0; r < 8; r++) {
            float xv = sX[(ty * 8 + r) * D + k];
            acc[r][0] += xv * w4.x; acc[r][1] += xv * w4.y;
            acc[r][2] += xv * w4.z; acc[r][3] += xv * w4.w;
        }
    }
    float4 b4 = ((const float4*)bias)[tx];
    float4 csum = make_float4(0.f, 0.f, 0.f, 0.f);
    #pragma unroll
    for (int r = 0; r < 8; r++) {
        int row = row0 + ty * 8 + r;
        if (row < n) {
            csum.x += tanhf(acc[r][0] + b4.x);
            csum.y += tanhf(acc[r][1] + b4.y);
            csum.z += tanhf(acc[r][2] + b4.z);
            csum.w += tanhf(acc[r][3] + b4.w);
        }
    }
    __syncthreads();                 // done reading sX, reuse as reduction buffer
    ((float4*)sX)[ty * 32 + tx] = csum;
    __syncthreads();
    if (ty == 0) {
        float4 s = make_float4(0.f, 0.f, 0.f, 0.f);
        #pragma unroll
        for (int g = 0; g < 8; g++) {
            float4 v = ((float4*)sX)[g * 32 + tx];
            s.x += v.x; s.y += v.y; s.z += v.z; s.w += v.w;
        }
        atomicAdd(&spout[4 * tx + 0], s.x);
        atomicAdd(&spout[4 * tx + 1], s.y);
        atomicAdd(&spout[4 * tx + 2], s.z);
        atomicAdd(&spout[4 * tx + 3], s.w);
    }
}

// ---------------- beta = softmax([att.sp0, att.sp1]) ---------------------------
__global__ void beta_kernel(const float* __restrict__ att) {
    __shared__ float r0[D], r1[D];
    int t = threadIdx.x;  // 128
    float inv = 1.f / (float)N_DST;
    r0[t] = att[t] * (g_sp[t] * inv);
    r1[t] = att[t] * (g_sp[D + t] * inv);
    __syncthreads();
    for (int o = 64; o; o >>= 1) {
        if (t < o) { r0[t] += r0[t + o]; r1[t] += r1[t + o]; }
        __syncthreads();
    }
    if (t == 0) {
        float x0 = r0[0], x1 = r1[0];
        float m  = fmaxf(x0, x1);
        float e0 = __expf(x0 - m), e1 = __expf(x1 - m);
        float s  = e0 + e1;
        g_beta[0] = e0 / s;
        g_beta[1] = e1 / s;
    }
}

// ---------------- out = beta0*e0 + beta1*e1 ------------------------------------
__global__ void combine_kernel(float* __restrict__ out) {
    float b0 = g_beta[0], b1 = g_beta[1];
    int total = N_DST * 32;  // float4 count
    const float4* e04 = (const float4*)g_e0;
    const float4* e14 = (const float4*)g_e1;
    float4*       o4  = (float4*)out;
    for (int i = blockIdx.x * blockDim.x + threadIdx.x; i < total;
         i += gridDim.x * blockDim.x) {
        float4 a = e04[i], b = e14[i];
        o4[i] = make_float4(b0 * a.x + b1 * b.x, b0 * a.y + b1 * b.y,
                            b0 * a.z + b1 * b.z, b0 * a.w + b1 * b.w);
    }
}

// ---------------- launch ------------------------------------------------------
extern "C" void kernel_launch(void* const* d_in, const int* in_sizes, int n_in,
                              void* d_out, int out_size) {
    const float* h_src0 = (const float*)d_in[0];
    const float* h_src1 = (const float*)d_in[1];
    const float* h_dst  = (const float*)d_in[2];
    const int*   idx0   = (const int*)d_in[3];
    const int*   idx1   = (const int*)d_in[4];
    const float* W_src0 = (const float*)d_in[5];
    const float* W_dst0 = (const float*)d_in[6];
    const float* a_l0   = (const float*)d_in[7];
    const float* a_r0   = (const float*)d_in[8];
    const float* b0     = (const float*)d_in[9];
    const float* W_src1 = (const float*)d_in[10];
    const float* W_dst1 = (const float*)d_in[11];
    const float* a_l1   = (const float*)d_in[12];
    const float* a_r1   = (const float*)d_in[13];
    const float* b1     = (const float*)d_in[14];
    const float* W_fc   = (const float*)d_in[15];
    const float* b_fc   = (const float*)d_in[16];
    const float* att    = (const float*)d_in[17];
    float*       out    = (float*)d_out;

    // device-global scratch addresses
    float *p_wl0, *p_wr0, *p_wl1, *p_wr1, *p_WfcT;
    float *p_el0, *p_el1, *p_er0, *p_er1, *p_agg0, *p_agg1, *p_e0, *p_e1, *p_sp;
    cudaGetSymbolAddress((void**)&p_wl0,  g_wl0);
    cudaGetSymbolAddress((void**)&p_wr0,  g_wr0);
    cudaGetSymbolAddress((void**)&p_wl1,  g_wl1);
    cudaGetSymbolAddress((void**)&p_wr1,  g_wr1);
    cudaGetSymbolAddress((void**)&p_WfcT, g_WfcT);
    cudaGetSymbolAddress((void**)&p_el0,  g_el0);
    cudaGetSymbolAddress((void**)&p_el1,  g_el1);
    cudaGetSymbolAddress((void**)&p_er0,  g_er0);
    cudaGetSymbolAddress((void**)&p_er1,  g_er1);
    cudaGetSymbolAddress((void**)&p_agg0, g_agg0);
    cudaGetSymbolAddress((void**)&p_agg1, g_agg1);
    cudaGetSymbolAddress((void**)&p_e0,   g_e0);
    cudaGetSymbolAddress((void**)&p_e1,   g_e1);
    cudaGetSymbolAddress((void**)&p_sp,   g_sp);

    const int GEMM_SMEM = (D * D + 64 * D) * sizeof(float);  // 98304
    cudaFuncSetAttribute(gemm_e,  cudaFuncAttributeMaxDynamicSharedMemorySize, GEMM_SMEM);
    cudaFuncSetAttribute(gemm_sp, cudaFuncAttributeMaxDynamicSharedMemorySize, GEMM_SMEM);

    // 1. prep (also zeroes sp accumulators; graph-replay safe)
    prep_kernel<<<1, 128>>>(W_src0, a_l0, W_dst0, a_r0, W_src1, a_l1, W_dst1, a_r1, W_fc);

    // 2. el / er GEMVs (one warp per row)
    gemv_el<<<(N_SRC0 * 32 + 255) / 256, 256>>>(h_src0, N_SRC0, p_wl0, p_el0);
    gemv_el<<<(N_SRC1 * 32 + 255) / 256, 256>>>(h_src1, N_SRC1, p_wl1, p_el1);
    gemv_er<<<(N_DST * 32 + 255) / 256, 256>>>(h_dst, p_wr0, p_wr1, p_er0, p_er1);

    // 3. gather + edge softmax + h-space aggregation
    gat_agg<K0><<<(N_DST * 32 + 255) / 256, 256>>>(h_src0, idx0, p_el0, p_er0, p_agg0);
    gat_agg<K1><<<(N_DST * 32 + 255) / 256, 256>>>(h_src1, idx1, p_el1, p_er1, p_agg1);

    // 4. e_r = agg_r @ W_src_r + b_r
    int gemm_blocks = (N_DST + 63) / 64;
    gemm_e<<<gemm_blocks, 256, GEMM_SMEM>>>(p_agg0, W_src0, b0, p_e0, N_DST);
    gemm_e<<<gemm_blocks, 256, GEMM_SMEM>>>(p_agg1, W_src1, b1, p_e1, N_DST);

    // 5. sp_r = sum_rows tanh(e_r @ Wfc^T + bfc)
    gemm_sp<<<gemm_blocks, 256, GEMM_SMEM>>>(p_e0, p_WfcT, b_fc, p_sp,     N_DST);
    gemm_sp<<<gemm_blocks, 256, GEMM_SMEM>>>(p_e1, p_WfcT, b_fc, p_sp + D, N_DST);

    // 6. beta
    beta_kernel<<<1, 128>>>(att);

    // 7. combine
    combine_kernel<<<12500, 256>>>(out);
}

// round 3
// speedup vs baseline: 1.0025x; 1.0025x over previous
#include <cuda_runtime.h>
#include <math.h>

#define D        128
#define N_DST    100000
#define N_SRC0   400000
#define N_SRC1   10000
#define K0       8
#define K1       4

// ---------------- scratch (device globals; no allocation allowed) ----------------
__device__ float g_wl0[D], g_wr0[D], g_wl1[D], g_wr1[D];
__device__ float g_WfcT[D * D];                    // WfcT[k*D+j] = Wfc[j*D+k]
__device__ float g_el0[N_SRC0];
__device__ float g_el1[N_SRC1];
__device__ float g_er0[N_DST];
__device__ float g_er1[N_DST];
__device__ float g_agg0[N_DST * D];
__device__ float g_agg1[N_DST * D];
__device__ float g_e0[N_DST * D];
__device__ float g_e1[N_DST * D];
__device__ float g_sp[2 * D];
__device__ float g_beta[2];

// ---------------- prep: w vectors, Wfc transpose, zero sp accumulators ----------
__global__ void prep_kernel(const float* __restrict__ Ws0, const float* __restrict__ al0,
                            const float* __restrict__ Wd0, const float* __restrict__ ar0,
                            const float* __restrict__ Ws1, const float* __restrict__ al1,
                            const float* __restrict__ Wd1, const float* __restrict__ ar1,
                            const float* __restrict__ Wfc) {
    int i = threadIdx.x;  // 0..127
    float s0 = 0.f, s1 = 0.f, s2 = 0.f, s3 = 0.f;
    for (int k = 0; k < D; k++) {
        s0 += Ws0[i * D + k] * al0[k];
        s1 += Wd0[i * D + k] * ar0[k];
        s2 += Ws1[i * D + k] * al1[k];
        s3 += Wd1[i * D + k] * ar1[k];
    }
    g_wl0[i] = s0; g_wr0[i] = s1; g_wl1[i] = s2; g_wr1[i] = s3;
    g_sp[i] = 0.f; g_sp[D + i] = 0.f;
    for (int j = 0; j < D; j++) g_WfcT[i * D + j] = Wfc[j * D + i];
}

// ---------------- GEMV: out[i] = dot(X[i,:], wv) -------------------------------
__global__ void gemv_el(const float* __restrict__ X, int n,
                        const float* __restrict__ wv, float* __restrict__ out) {
    __shared__ float4 sw[32];
    int t = threadIdx.x;
    if (t < 32) sw[t] = ((const float4*)wv)[t];
    __syncthreads();
    int lane = t & 31;
    int row  = (blockIdx.x * blockDim.x + t) >> 5;
    if (row >= n) return;
    float4 x  = ((const float4*)X)[row * 32 + lane];
    float4 w  = sw[lane];
    float  s  = x.x * w.x + x.y * w.y + x.z * w.z + x.w * w.w;
    #pragma unroll
    for (int o = 16; o; o >>= 1) s += __shfl_xor_sync(0xffffffffu, s, o);
    if (lane == 0) out[row] = s;
}

// ---------------- GEMV x2: er0/er1 from h_dst in one pass ----------------------
__global__ void gemv_er(const float* __restrict__ X,
                        const float* __restrict__ wv0, const float* __restrict__ wv1,
                        float* __restrict__ out0, float* __restrict__ out1) {
    __shared__ float4 sw0[32], sw1[32];
    int t = threadIdx.x;
    if (t < 32) { sw0[t] = ((const float4*)wv0)[t]; sw1[t] = ((const float4*)wv1)[t]; }
    __syncthreads();
    int lane = t & 31;
    int row  = (blockIdx.x * blockDim.x + t) >> 5;
    if (row >= N_DST) return;
    float4 x  = ((const float4*)X)[row * 32 + lane];
    float4 w0 = sw0[lane], w1 = sw1[lane];
    float  s0 = x.x * w0.x + x.y * w0.y + x.z * w0.z + x.w * w0.w;
    float  s1 = x.x * w1.x + x.y * w1.y + x.z * w1.z + x.w * w1.w;
    #pragma unroll
    for (int o = 16; o; o >>= 1) {
        s0 += __shfl_xor_sync(0xffffffffu, s0, o);
        s1 += __shfl_xor_sync(0xffffffffu, s1, o);
    }
    if (lane == 0) { out0[row] = s0; out1[row] = s1; }
}

// ---------------- gather + edge softmax + h-space aggregation ------------------
template <int K>
__global__ void gat_agg(const float* __restrict__ hsrc, const int* __restrict__ idx,
                        const float* __restrict__ el, const float* __restrict__ er,
                        float* __restrict__ agg) {
    int t    = threadIdx.x;
    int lane = t & 31;
    int row  = (blockIdx.x * blockDim.x + t) >> 5;
    if (row >= N_DST) return;

    int   id = 0;
    float e  = 0.f;
    if (lane < K) {
        id = idx[row * K + lane];
        e  = el[id] + er[row];
        e  = e > 0.f ? e : 0.2f * e;   // leaky relu 0.2
    }
    float m = -1e30f;
    #pragma unroll
    for (int j = 0; j < K; j++) m = fmaxf(m, __shfl_sync(0xffffffffu, e, j));
    float a[K];
    float denom = 0.f;
    #pragma unroll
    for (int j = 0; j < K; j++) {
        a[j] = __expf(__shfl_sync(0xffffffffu, e, j) - m);
        denom += a[j];
    }
    float inv = 1.f / denom;
    float4 acc = make_float4(0.f, 0.f, 0.f, 0.f);
    #pragma unroll
    for (int j = 0; j < K; j++) {
        int    ij = __shfl_sync(0xffffffffu, id, j);
        float4 x  = ((const float4*)hsrc)[ij * 32 + lane];
        float  aj = a[j] * inv;
        acc.x += aj * x.x; acc.y += aj * x.y; acc.z += aj * x.z; acc.w += aj * x.w;
    }
    ((float4*)agg)[row * 32 + lane] = acc;
}

// ---------------- GEMM: Y[n,128] = X[n,128] @ W[128,128] + bias ----------------
// block: 256 threads; tile 64 rows; thread (tx=t%32 -> 4 cols, ty=t/32 -> 8 rows)
__global__ void gemm_e(const float* __restrict__ X, const float* __restrict__ W,
                       const float* __restrict__ bias, float* __restrict__ Y, int n) {
    extern __shared__ float smem[];
    float* sW = smem;            // 128*128
    float* sX = smem + D * D;    // 64*128
    int t = threadIdx.x;
    {
        float4*       sW4 = (float4*)sW;
        const float4* W4  = (const float4*)W;
        for (int i = t; i < D * D / 4; i += 256) sW4[i] = W4[i];
    }
    int tx   = t & 31;
    int ty   = t >> 5;
    int row0 = blockIdx.x * 64;
    {
        const float4* X4  = (const float4*)X;
        float4*       sX4 = (float4*)sX;
        for (int i = t; i < 64 * 32; i += 256) {
            int r = i >> 5, c = i & 31;
            float4 v = make_float4(0.f, 0.f, 0.f, 0.f);
            if (row0 + r < n) v = X4[(row0 + r) * 32 + c];
            sX4[i] = v;
        }
    }
    __syncthreads();
    float acc[8][4];
    #pragma unroll
    for (int r = 0; r < 8; r++)
        #pragma unroll
        for (int c = 0; c < 4; c++) acc[r][c] = 0.f;

    const float4* sW4 = (const float4*)sW;
    #pragma unroll 4
    for (int k = 0; k < D; k++) {
        float4 w4 = sW4[k * 32 + tx];
        #pragma unroll
        for (int r = 0; r < 8; r++) {
            float xv = sX[(ty * 8 + r) * D + k];
            acc[r][0] += xv * w4.x; acc[r][1] += xv * w4.y;
            acc[r][2] += xv * w4.z; acc[r][3] += xv * w4.w;
        }
    }
    float4 b4 = ((const float4*)bias)[tx];
    #pragma unroll
    for (int r = 0; r < 8; r++) {
        int row = row0 + ty * 8 + r;
        if (row < n) {
            float4 o = make_float4(acc[r][0] + b4.x, acc[r][1] + b4.y,
                                   acc[r][2] + b4.z, acc[r][3] + b4.w);
            ((float4*)Y)[row * 32 + tx] = o;
        }
    }
}

// ---------------- GEMM + tanh + column-mean accumulation -----------------------
// sp += sum_rows tanh(X @ WfcT_cols + bias)   (Wt is already transposed: Wt[k*D+j])
__global__ void gemm_sp(const float* __restrict__ X, const float* __restrict__ Wt,
                        const float* __restrict__ bias, float* __restrict__ spout, int n) {
    extern __shared__ float smem[];
    float* sW = smem;
    float* sX = smem + D * D;
    int t = threadIdx.x;
    {
        float4*       sW4 = (float4*)sW;
        const float4* W4  = (const float4*)Wt;
        for (int i = t; i < D * D / 4; i += 256) sW4[i] = W4[i];
    }
    int tx   = t & 31;
    int ty   = t >> 5;
    int row0 = blockIdx.x * 64;
    {
        const float4* X4  = (const float4*)X;
        float4*       sX4 = (float4*)sX;
        for (int i = t; i < 64 * 32; i += 256) {
            int r = i >> 5, c = i & 31;
            float4 v = make_float4(0.f, 0.f, 0.f, 0.f);
            if (row0 + r < n) v = X4[(row0 + r) * 32 + c];
            sX4[i] = v;
        }
    }
    __syncthreads();
    float acc[8][4];
    #pragma unroll
    for (int r = 0; r < 8; r++)
        #pragma unroll
        for (int c = 0; c < 4; c++) acc[r][c] = 0.f;

    const float4* sW4 = (const float4*)sW;
    #pragma unroll 4
    for (int k = 0; k < D; k++) {
        float4 w4 = sW4[k * 32 + tx];
        #pragma unroll
        for (int r = 0; r < 8; r++) {
            float xv = sX[(ty * 8 + r) * D + k];
            acc[r][0] += xv * w4.x; acc[r][1] += xv * w4.y;
            acc[r][2] += xv * w4.z; acc[r][3] += xv * w4.w;
        }
    }
    float4 b4 = ((const float4*)bias)[tx];
    float4 csum = make_float4(0.f, 0.f, 0.f, 0.f);
    #pragma unroll
    for (int r = 0; r < 8; r++) {
        int row = row0 + ty * 8 + r;
        if (row < n) {
            csum.x += tanhf(acc[r][0] + b4.x);
            csum.y += tanhf(acc[r][1] + b4.y);
            csum.z += tanhf(acc[r][2] + b4.z);
            csum.w += tanhf(acc[r][3] + b4.w);
        }
    }
    __syncthreads();                 // done reading sX, reuse as reduction buffer
    ((float4*)sX)[ty * 32 + tx] = csum;
    __syncthreads();
    if (ty == 0) {
        float4 s = make_float4(0.f, 0.f, 0.f, 0.f);
        #pragma unroll
        for (int g = 0; g < 8; g++) {
            float4 v = ((float4*)sX)[g * 32 + tx];
            s.x += v.x; s.y += v.y; s.z += v.z; s.w += v.w;
        }
        atomicAdd(&spout[4 * tx + 0], s.x);
        atomicAdd(&spout[4 * tx + 1], s.y);
        atomicAdd(&spout[4 * tx + 2], s.z);
        atomicAdd(&spout[4 * tx + 3], s.w);
    }
}

// ---------------- beta = softmax([att.sp0, att.sp1]) ---------------------------
__global__ void beta_kernel(const float* __restrict__ att) {
    __shared__ float r0[D], r1[D];
    int t = threadIdx.x;  // 128
    float inv = 1.f / (float)N_DST;
    r0[t] = att[t] * (g_sp[t] * inv);
    r1[t] = att[t] * (g_sp[D + t] * inv);
    __syncthreads();
    for (int o = 64; o; o >>= 1) {
        if (t < o) { r0[t] += r0[t + o]; r1[t] += r1[t + o]; }
        __syncthreads();
    }
    if (t == 0) {
        float x0 = r0[0], x1 = r1[0];
        float m  = fmaxf(x0, x1);
        float e0 = __expf(x0 - m), e1 = __expf(x1 - m);
        float s  = e0 + e1;
        g_beta[0] = e0 / s;
        g_beta[1] = e1 / s;
    }
}

// ---------------- out = beta0*e0 + beta1*e1 ------------------------------------
__global__ void combine_kernel(float* __restrict__ out) {
    float b0 = g_beta[0], b1 = g_beta[1];
    int total = N_DST * 32;  // float4 count
    const float4* e04 = (const float4*)g_e0;
    const float4* e14 = (const float4*)g_e1;
    float4*       o4  = (float4*)out;
    for (int i = blockIdx.x * blockDim.x + threadIdx.x; i < total;
         i += gridDim.x * blockDim.x) {
        float4 a = e04[i], b = e14[i];
        o4[i] = make_float4(b0 * a.x + b1 * b.x, b0 * a.y + b1 * b.y,
                            b0 * a.z + b1 * b.z, b0 * a.w + b1 * b.w);
    }
}

// ---------------- launch ------------------------------------------------------
extern "C" void kernel_launch(void* const* d_in, const int* in_sizes, int n_in,
                              void* d_out, int out_size) {
    const float* h_src0 = (const float*)d_in[0];
    const float* h_src1 = (const float*)d_in[1];
    const float* h_dst  = (const float*)d_in[2];
    const int*   idx0   = (const int*)d_in[3];
    const int*   idx1   = (const int*)d_in[4];
    const float* W_src0 = (const float*)d_in[5];
    const float* W_dst0 = (const float*)d_in[6];
    const float* a_l0   = (const float*)d_in[7];
    const float* a_r0   = (const float*)d_in[8];
    const float* b0     = (const float*)d_in[9];
    const float* W_src1 = (const float*)d_in[10];
    const float* W_dst1 = (const float*)d_in[11];
    const float* a_l1   = (const float*)d_in[12];
    const float* a_r1   = (const float*)d_in[13];
    const float* b1     = (const float*)d_in[14];
    const float* W_fc   = (const float*)d_in[15];
    const float* b_fc   = (const float*)d_in[16];
    const float* att    = (const float*)d_in[17];
    float*       out    = (float*)d_out;

    // device-global scratch addresses
    float *p_wl0, *p_wr0, *p_wl1, *p_wr1, *p_WfcT;
    float *p_el0, *p_el1, *p_er0, *p_er1, *p_agg0, *p_agg1, *p_e0, *p_e1, *p_sp;
    cudaGetSymbolAddress((void**)&p_wl0,  g_wl0);
    cudaGetSymbolAddress((void**)&p_wr0,  g_wr0);
    cudaGetSymbolAddress((void**)&p_wl1,  g_wl1);
    cudaGetSymbolAddress((void**)&p_wr1,  g_wr1);
    cudaGetSymbolAddress((void**)&p_WfcT, g_WfcT);
    cudaGetSymbolAddress((void**)&p_el0,  g_el0);
    cudaGetSymbolAddress((void**)&p_el1,  g_el1);
    cudaGetSymbolAddress((void**)&p_er0,  g_er0);
    cudaGetSymbolAddress((void**)&p_er1,  g_er1);
    cudaGetSymbolAddress((void**)&p_agg0, g_agg0);
    cudaGetSymbolAddress((void**)&p_agg1, g_agg1);
    cudaGetSymbolAddress((void**)&p_e0,   g_e0);
    cudaGetSymbolAddress((void**)&p_e1,   g_e1);
    cudaGetSymbolAddress((void**)&p_sp,   g_sp);

    const int GEMM_SMEM = (D * D + 64 * D) * sizeof(float);  // 98304
    cudaFuncSetAttribute(gemm_e,  cudaFuncAttributeMaxDynamicSharedMemorySize, GEMM_SMEM);
    cudaFuncSetAttribute(gemm_sp, cudaFuncAttributeMaxDynamicSharedMemorySize, GEMM_SMEM);

    // 1. prep (also zeroes sp accumulators; graph-replay safe)
    prep_kernel<<<1, 128>>>(W_src0, a_l0, W_dst0, a_r0, W_src1, a_l1, W_dst1, a_r1, W_fc);

    // 2. el / er GEMVs (one warp per row)
    gemv_el<<<(N_SRC0 * 32 + 255) / 256, 256>>>(h_src0, N_SRC0, p_wl0, p_el0);
    gemv_el<<<(N_SRC1 * 32 + 255) / 256, 256>>>(h_src1, N_SRC1, p_wl1, p_el1);
    gemv_er<<<(N_DST * 32 + 255) / 256, 256>>>(h_dst, p_wr0, p_wr1, p_er0, p_er1);

    // 3. gather + edge softmax + h-space aggregation
    gat_agg<K0><<<(N_DST * 32 + 255) / 256, 256>>>(h_src0, idx0, p_el0, p_er0, p_agg0);
    gat_agg<K1><<<(N_DST * 32 + 255) / 256, 256>>>(h_src1, idx1, p_el1, p_er1, p_agg1);

    // 4. e_r = agg_r @ W_src_r + b_r
    int gemm_blocks = (N_DST + 63) / 64;
    gemm_e<<<gemm_blocks, 256, GEMM_SMEM>>>(p_agg0, W_src0, b0, p_e0, N_DST);
    gemm_e<<<gemm_blocks, 256, GEMM_SMEM>>>(p_agg1, W_src1, b1, p_e1, N_DST);

    // 5. sp_r = sum_rows tanh(e_r @ Wfc^T + bfc)
    gemm_sp<<<gemm_blocks, 256, GEMM_SMEM>>>(p_e0, p_WfcT, b_fc, p_sp,     N_DST);
    gemm_sp<<<gemm_blocks, 256, GEMM_SMEM>>>(p_e1, p_WfcT, b_fc, p_sp + D, N_DST);

    // 6. beta
    beta_kernel<<<1, 128>>>(att);

    // 7. combine
    combine_kernel<<<12500, 256>>>(out);
}